// round 2
// baseline (speedup 1.0000x reference)
#include <cuda_runtime.h>

#define N_NODES   200000
#define N_EDGES   3200000
#define N_GRAPHS  1024

// ---------------- scratch (static device globals; no allocation) ------------
__device__ float g_A[N_NODES * 64];     // activations (layer input)
__device__ float g_B[N_NODES * 64];     // hs = (in @ W) * dinv
__device__ float g_C[N_NODES * 64];     // acc (scatter destination)
__device__ float g_dinv[N_NODES];
__device__ int   g_deg[N_NODES];
__device__ int2  g_edges[N_EDGES];      // int32 (src,dst)
__device__ float g_gmax[N_GRAPHS * 32];
__device__ float g_gsum[N_GRAPHS * 32];
__device__ float g_cnt[N_GRAPHS];
__device__ int   g_idx64;               // 1 if index inputs are int64, 0 if int32

// ---------------- kernels ---------------------------------------------------

// Probe index dtype: if first 16 values interpreted as int64 are all valid node
// ids, the buffer is int64; otherwise it is int32 (two packed int32s make a
// huge int64 whenever the second value is nonzero — true w.h.p. for random ids).
__global__ void detect_kernel(const void* __restrict__ ei) {
    const long long* p = (const long long*)ei;
    int ok = 1;
#pragma unroll
    for (int i = 0; i < 16; i++) {
        long long v = p[i];
        if (v < 0 || v >= N_NODES) ok = 0;
    }
    g_idx64 = ok;
}

__global__ void init_kernel() {
    int i = blockIdx.x * blockDim.x + threadIdx.x;
    if (i < N_NODES) g_deg[i] = 1;                 // self-loop
    if (i < N_GRAPHS * 32) { g_gmax[i] = 0.0f; g_gsum[i] = 0.0f; }
    if (i < N_GRAPHS) g_cnt[i] = 0.0f;
}

__global__ void edge_prep(const void* __restrict__ ei) {
    int e = blockIdx.x * blockDim.x + threadIdx.x;
    if (e >= N_EDGES) return;
    int s, d;
    if (g_idx64) {
        const long long* p = (const long long*)ei;
        s = (int)p[e];
        d = (int)p[N_EDGES + e];
    } else {
        const int* p = (const int*)ei;
        s = p[e];
        d = p[N_EDGES + e];
    }
    g_edges[e] = make_int2(s, d);
    atomicAdd(&g_deg[d], 1);
}

__global__ void dinv_kernel() {
    int i = blockIdx.x * blockDim.x + threadIdx.x;
    if (i < N_NODES) g_dinv[i] = rsqrtf((float)g_deg[i]);
}

// hs = (in @ W) * dinv, written to both hs buffer and acc buffer (self-loop init).
// NO/4 threads per node, each computes 4 consecutive outputs.
template <int K, int NO>
__global__ void gemm_scale(const float* __restrict__ in, const float* __restrict__ W,
                           float* __restrict__ hs, float* __restrict__ acc) {
    __shared__ float sW[K * NO];
    for (int i = threadIdx.x; i < K * NO; i += blockDim.x) sW[i] = W[i];
    __syncthreads();
    const int TPN = NO / 4;
    int gid  = blockIdx.x * blockDim.x + threadIdx.x;
    int node = gid / TPN;
    int oc   = (gid % TPN) * 4;
    if (node >= N_NODES) return;
    const float* xr = in + (size_t)node * K;
    float a0 = 0.f, a1 = 0.f, a2 = 0.f, a3 = 0.f;
#pragma unroll
    for (int k = 0; k < K; k++) {
        float xv = __ldg(xr + k);
        float4 w = *(const float4*)(sW + k * NO + oc);
        a0 += xv * w.x; a1 += xv * w.y; a2 += xv * w.z; a3 += xv * w.w;
    }
    float dv = g_dinv[node];
    float4 v = make_float4(a0 * dv, a1 * dv, a2 * dv, a3 * dv);
    *(float4*)(hs  + (size_t)node * NO + oc) = v;
    *(float4*)(acc + (size_t)node * NO + oc) = v;
}

// Edge scatter: acc[dst] += hs[src]. NO/4 threads per edge, vector atomics.
template <int NO>
__global__ void scatter_kernel(const float* __restrict__ hs, float* __restrict__ acc) {
    const int TPE = NO / 4;
    int gid  = blockIdx.x * blockDim.x + threadIdx.x;
    int e    = gid / TPE;
    int lane = gid % TPE;
    if (e >= N_EDGES) return;
    int2 ed = g_edges[e];                                // broadcast load
    float4 v = *(const float4*)(hs + (size_t)ed.x * NO + lane * 4);
    float* p = acc + (size_t)ed.y * NO + lane * 4;
    asm volatile("red.global.add.v4.f32 [%0], {%1,%2,%3,%4};"
                 :: "l"(p), "f"(v.x), "f"(v.y), "f"(v.z), "f"(v.w)
                 : "memory");
}

// out = act(dinv * acc + b)
template <int NO, bool IS_TANH>
__global__ void act_kernel(const float* __restrict__ acc, const float* __restrict__ b,
                           float* __restrict__ out) {
    const int TPN = NO / 4;
    int gid  = blockIdx.x * blockDim.x + threadIdx.x;
    int node = gid / TPN;
    int oc   = (gid % TPN) * 4;
    if (node >= N_NODES) return;
    float dv  = g_dinv[node];
    float4 c  = *(const float4*)(acc + (size_t)node * NO + oc);
    float4 bb = *(const float4*)(b + oc);
    float4 r;
    r.x = fmaf(dv, c.x, bb.x);
    r.y = fmaf(dv, c.y, bb.y);
    r.z = fmaf(dv, c.z, bb.z);
    r.w = fmaf(dv, c.w, bb.w);
    if (IS_TANH) {
        r.x = tanhf(r.x); r.y = tanhf(r.y); r.z = tanhf(r.z); r.w = tanhf(r.w);
    } else {
        r.x = fmaxf(r.x, 0.f); r.y = fmaxf(r.y, 0.f);
        r.z = fmaxf(r.z, 0.f); r.w = fmaxf(r.w, 0.f);
    }
    *(float4*)(out + (size_t)node * NO + oc) = r;
}

// Segment max + sum + count over graphs (final width 32). 8 threads/node.
// atomicMax on float-as-int is valid: all values are post-ReLU >= 0, init 0.
__global__ void pool_kernel(const float* __restrict__ h, const void* __restrict__ batch) {
    int gid  = blockIdx.x * blockDim.x + threadIdx.x;
    int node = gid / 8;
    int lane = gid % 8;
    if (node >= N_NODES) return;
    int g;
    if (g_idx64) g = (int)((const long long*)batch)[node];
    else         g = ((const int*)batch)[node];
    float4 v = *(const float4*)(h + (size_t)node * 32 + lane * 4);
    int base = g * 32 + lane * 4;
    atomicMax((int*)&g_gmax[base + 0], __float_as_int(v.x));
    atomicMax((int*)&g_gmax[base + 1], __float_as_int(v.y));
    atomicMax((int*)&g_gmax[base + 2], __float_as_int(v.z));
    atomicMax((int*)&g_gmax[base + 3], __float_as_int(v.w));
    float* p = &g_gsum[base];
    asm volatile("red.global.add.v4.f32 [%0], {%1,%2,%3,%4};"
                 :: "l"(p), "f"(v.x), "f"(v.y), "f"(v.z), "f"(v.w)
                 : "memory");
    if (lane == 0) atomicAdd(&g_cnt[g], 1.0f);
}

// out[g, o] = bout[o] + sum_f gmax[g,f]*Wout[f,o] + sum_f gmean[g,f]*Wout[32+f,o]
__global__ void final_kernel(const float* __restrict__ Wout, const float* __restrict__ bout,
                             float* __restrict__ out) {
    int idx = blockIdx.x * blockDim.x + threadIdx.x;
    if (idx >= N_GRAPHS * 10) return;
    int g = idx / 10, o = idx % 10;
    float inv = 1.0f / fmaxf(g_cnt[g], 1.0f);
    float s = bout[o];
#pragma unroll
    for (int f = 0; f < 32; f++) s = fmaf(g_gmax[g * 32 + f], Wout[f * 10 + o], s);
#pragma unroll
    for (int f = 0; f < 32; f++) s = fmaf(g_gsum[g * 32 + f] * inv, Wout[(32 + f) * 10 + o], s);
    out[idx] = s;
}

// ---------------- launch -----------------------------------------------------

extern "C" void kernel_launch(void* const* d_in, const int* in_sizes, int n_in,
                              void* d_out, int out_size) {
    const float* x     = (const float*)d_in[0];
    const void*  ei    = d_in[1];
    const void*  batch = d_in[2];
    const float* W0 = (const float*)d_in[3];  const float* b0 = (const float*)d_in[4];
    const float* W1 = (const float*)d_in[5];  const float* b1 = (const float*)d_in[6];
    const float* W2 = (const float*)d_in[7];  const float* b2 = (const float*)d_in[8];
    const float* W3 = (const float*)d_in[9];  const float* b3 = (const float*)d_in[10];
    const float* Wout = (const float*)d_in[11];
    const float* bout = (const float*)d_in[12];
    float* out = (float*)d_out;

    float *A, *B, *C;
    cudaGetSymbolAddress((void**)&A, g_A);
    cudaGetSymbolAddress((void**)&B, g_B);
    cudaGetSymbolAddress((void**)&C, g_C);

    const int T = 256;
    const int NB_N   = (N_NODES + T - 1) / T;
    const int NB_E   = (N_EDGES + T - 1) / T;
    const int NB_N16 = (N_NODES * 16 + T - 1) / T;
    const int NB_N8  = (N_NODES * 8 + T - 1) / T;
    const int NB_E16 = (int)(((long long)N_EDGES * 16 + T - 1) / T);
    const int NB_E8  = (int)(((long long)N_EDGES * 8 + T - 1) / T);

    detect_kernel<<<1, 1>>>(ei);
    init_kernel<<<NB_N, T>>>();
    edge_prep<<<NB_E, T>>>(ei);
    dinv_kernel<<<NB_N, T>>>();

    // Layer 0: 8 -> 64, tanh
    gemm_scale<8, 64><<<NB_N16, T>>>(x, W0, B, C);
    scatter_kernel<64><<<NB_E16, T>>>(B, C);
    act_kernel<64, true><<<NB_N16, T>>>(C, b0, A);

    // Layer 1: 64 -> 64, relu
    gemm_scale<64, 64><<<NB_N16, T>>>(A, W1, B, C);
    scatter_kernel<64><<<NB_E16, T>>>(B, C);
    act_kernel<64, false><<<NB_N16, T>>>(C, b1, A);

    // Layer 2: 64 -> 32, relu
    gemm_scale<64, 32><<<NB_N8, T>>>(A, W2, B, C);
    scatter_kernel<32><<<NB_E8, T>>>(B, C);
    act_kernel<32, false><<<NB_N8, T>>>(C, b2, A);

    // Layer 3: 32 -> 32, relu
    gemm_scale<32, 32><<<NB_N8, T>>>(A, W3, B, C);
    scatter_kernel<32><<<NB_E8, T>>>(B, C);
    act_kernel<32, false><<<NB_N8, T>>>(C, b3, A);

    pool_kernel<<<NB_N8, T>>>(A, batch);
    final_kernel<<<(N_GRAPHS * 10 + T - 1) / T, T>>>(Wout, bout, out);
}